// round 14
// baseline (speedup 1.0000x reference)
#include <cuda_runtime.h>
#include <cuda_fp16.h>
#include <cstdint>

// ArcFace loss, fused. FP16 HMMA (m16n8k16.f16), warp tile 64x64, fp16 acc.
// This round: numerator computed in k1 (per-row, pre-GEMM); exclusive sums
// accumulated via double atomicAdd in k2's epilogue; k3 reduced to a single
// tiny block. k2 mainloop identical to the 151.6us best.
// B=512, D=512, C=64000.
constexpr int BB = 512;
constexpr int DD = 512;
constexpr int CC = 64000;

constexpr int BM = 256, BN = 128, BK = 32;
constexpr int MT = BB / BM;    // 2
constexpr int NT = CC / BN;    // 500
constexpr int NSTG = DD / BK;  // 16
constexpr int AROW = 40;       // smem row stride (halfs); ldsm conflict-free
constexpr int A_STG = BM * AROW * 2;   // 20480 B
constexpr int B_STG = BN * AROW * 2;   // 10240 B
constexpr int NPIPE = 3;

// dynamic smem layout
constexpr int A_OFF  = 0;                       // 3 stages
constexpr int B_OFF  = NPIPE * A_STG;           // 61440, 3 stages
constexpr int SY_OFF = B_OFF + NPIPE * B_STG;   // 92160: 256 ints
constexpr int RA_OFF = SY_OFF + 1024;           // 93184: 256x2 floats
constexpr int SMEM_TOTAL = RA_OFF + 2048;       // 95232 (x2 CTA = 190KB <= 228KB)

__device__ __half g_xnh[BB * DD];   // normalized x fp16 (GEMM A)
__device__ __half g_wnh[CC * DD];   // normalized W fp16 (GEMM B)
__device__ int    g_y[BB];
__device__ double g_num[BB];        // per-row numerator (from k1)
__device__ double g_excl[BB];       // per-row exclusive exp-sum (k2 atomics)

// ---------------- PTX helpers ----------------
__device__ __forceinline__ void ldsm4(uint32_t* r, uint32_t a) {
    asm volatile("ldmatrix.sync.aligned.m8n8.x4.shared.b16 {%0,%1,%2,%3}, [%4];"
        : "=r"(r[0]), "=r"(r[1]), "=r"(r[2]), "=r"(r[3]) : "r"(a));
}
__device__ __forceinline__ void mma16816h(uint32_t* c, const uint32_t* a, uint32_t b0, uint32_t b1) {
    asm volatile("mma.sync.aligned.m16n8k16.row.col.f16.f16.f16.f16 "
        "{%0,%1}, {%2,%3,%4,%5}, {%6,%7}, {%0,%1};"
        : "+r"(c[0]), "+r"(c[1])
        : "r"(a[0]), "r"(a[1]), "r"(a[2]), "r"(a[3]), "r"(b0), "r"(b1));
}
__device__ __forceinline__ void cpasync16(uint32_t smem, const void* gptr) {
    asm volatile("cp.async.cg.shared.global [%0], [%1], 16;"
        :: "r"(smem), "l"(gptr) : "memory");
}
__device__ __forceinline__ void cpcommit() { asm volatile("cp.async.commit_group;" ::: "memory"); }
__device__ __forceinline__ void cpwait1() { asm volatile("cp.async.wait_group 1;" ::: "memory"); }

// ---------------------------------------------------------------------------
// k0: decode labels (int64 vs int32 layout sniff) + zero the atomic buffers.
// ---------------------------------------------------------------------------
__global__ void k0_init(const int* __restrict__ yw) {
    __shared__ int oddnz;
    int t = threadIdx.x; // 512
    if (t == 0) oddnz = 0;
    __syncthreads();
    if (t < 256 && yw[2 * t + 1] != 0) atomicOr(&oddnz, 1);
    __syncthreads();
    g_y[t] = oddnz ? yw[t] : (int)((const long long*)yw)[t];
    g_excl[t] = 0.0;
}

// ---------------------------------------------------------------------------
// k1: per-row: L2-normalize x -> fp16 AND compute the exact numerator:
// num = 64*cos(acos(clip(x̂·W_y/|W_y|)) + 0.5), all from fp32 inputs.
// 512 blocks x 128 threads.
// ---------------------------------------------------------------------------
__global__ void k1_norm_x(const float* __restrict__ x, const float* __restrict__ Wm) {
    int row = blockIdx.x;
    int t = threadIdx.x; // 128
    int yb = g_y[row];
    float4 v  = ((const float4*)(x + row * DD))[t];
    float4 wv = ((const float4*)(Wm + (size_t)yb * DD))[t];
    float ss  = v.x * v.x + v.y * v.y + v.z * v.z + v.w * v.w;
    float dr  = wv.x * v.x + wv.y * v.y + wv.z * v.z + wv.w * v.w;
    float wss = wv.x * wv.x + wv.y * wv.y + wv.z * wv.z + wv.w * wv.w;
    #pragma unroll
    for (int o = 16; o; o >>= 1) {
        ss  += __shfl_xor_sync(0xffffffffu, ss, o);
        dr  += __shfl_xor_sync(0xffffffffu, dr, o);
        wss += __shfl_xor_sync(0xffffffffu, wss, o);
    }
    __shared__ float ws[4], wd[4], ww[4];
    if ((t & 31) == 0) { ws[t >> 5] = ss; wd[t >> 5] = dr; ww[t >> 5] = wss; }
    __syncthreads();
    float tot = ws[0] + ws[1] + ws[2] + ws[3];
    float sc = 1.0f / fmaxf(sqrtf(tot), 1e-12f);
    __half2 p0 = __floats2half2_rn(v.x * sc, v.y * sc);
    __half2 p1 = __floats2half2_rn(v.z * sc, v.w * sc);
    ((__half2*)(g_xnh + row * DD))[2 * t]     = p0;
    ((__half2*)(g_xnh + row * DD))[2 * t + 1] = p1;

    if (t == 0) {
        float dsum = wd[0] + wd[1] + wd[2] + wd[3];
        float wsum = ww[0] + ww[1] + ww[2] + ww[3];
        double tgt = (double)(dsum * sc) / fmax(sqrt((double)wsum), 1e-12);
        double tc = fmin(fmax(tgt, -1.0 + 1e-7), 1.0 - 1e-7);
        g_num[row] = 64.0 * cos(acos(tc) + 0.5);
    }
}

// k1b: L2-normalize rows of W -> fp16. One warp per row, 8 rows per block.
__global__ __launch_bounds__(256) void k1b_norm_w(const float* __restrict__ Wm) {
    int wid = threadIdx.x >> 5, lane = threadIdx.x & 31;
    int row = blockIdx.x * 8 + wid;
    const float4* wr = (const float4*)(Wm + (size_t)row * DD);
    float4 v[4];
    float ss = 0.f;
    #pragma unroll
    for (int i = 0; i < 4; i++) {
        v[i] = wr[lane + i * 32];
        ss += v[i].x * v[i].x + v[i].y * v[i].y + v[i].z * v[i].z + v[i].w * v[i].w;
    }
    #pragma unroll
    for (int o = 16; o; o >>= 1) ss += __shfl_xor_sync(0xffffffffu, ss, o);
    float sc = 1.0f / fmaxf(sqrtf(ss), 1e-12f);
    __half2* out = (__half2*)(g_wnh + (size_t)row * DD);
    #pragma unroll
    for (int i = 0; i < 4; i++) {
        __half2 p0 = __floats2half2_rn(v[i].x * sc, v[i].y * sc);
        __half2 p1 = __floats2half2_rn(v[i].z * sc, v[i].w * sc);
        out[(lane + i * 32) * 2]     = p0;
        out[(lane + i * 32) * 2 + 1] = p1;
    }
}

// ---------------------------------------------------------------------------
// k2: fp16 HMMA GEMM, 256 threads / 8 warps (4x2, warp tile 64x64), 256Mx128N,
// BK=32, 3-stage cp.async (single sync/stage), 2 CTAs/SM. Epilogue RED-adds
// per-row exclusive sums into g_excl (double).
// ---------------------------------------------------------------------------
__global__ __launch_bounds__(256, 2) void k2_gemm() {
    extern __shared__ char smem[];
    const uint32_t sb = (uint32_t)__cvta_generic_to_shared(smem);
    const int t = threadIdx.x, lane = t & 31, wp = t >> 5;
    const int wm = wp >> 1, wn = wp & 1;       // 4x2 warps, tile 64x64
    const int mt = blockIdx.x, nt = blockIdx.y;
    const int m0 = mt * BM, n0 = nt * BN;

    if (t < BM) ((int*)(smem + SY_OFF))[t] = g_y[m0 + t];

    // producers: A 4 rows/thread (stride 64), B 2 rows/thread (stride 64)
    const int pr = t >> 2, pc = (t & 3) * 8;
    const __half* gA = g_xnh + (m0 + pr) * DD + pc;
    const __half* gB = g_wnh + (size_t)(n0 + pr) * DD + pc;
    const uint32_t sA = sb + A_OFF + (pr * AROW + pc) * 2;
    const uint32_t sB = sb + B_OFF + (pr * AROW + pc) * 2;
    constexpr uint32_t ARS = 64 * AROW * 2;   // 64-row stride in smem bytes
    uint32_t woA = 0, woB = 0;

    auto fill = [&]() {
        cpasync16(sA + woA,           gA);
        cpasync16(sA + woA + ARS,     gA + 64 * DD);
        cpasync16(sA + woA + 2 * ARS, gA + 128 * DD);
        cpasync16(sA + woA + 3 * ARS, gA + 192 * DD);
        cpasync16(sB + woB,           gB);
        cpasync16(sB + woB + ARS,     gB + 64 * DD);
        gA += BK; gB += BK;
        woA += A_STG; if (woA == NPIPE * A_STG) woA = 0;
        woB += B_STG; if (woB == NPIPE * B_STG) woB = 0;
    };

    uint32_t acc[4][8][2];   // fp16x2 accumulators, 64 regs
    #pragma unroll
    for (int i = 0; i < 4; i++)
        #pragma unroll
        for (int j = 0; j < 8; j++) { acc[i][j][0] = 0u; acc[i][j][1] = 0u; }

    uint32_t aoff[4], boff[4];
    #pragma unroll
    for (int mf = 0; mf < 4; mf++)
        aoff[mf] = sb + A_OFF + ((wm * 64 + mf * 16 + (lane & 15)) * AROW + (lane >> 4) * 8) * 2;
    #pragma unroll
    for (int g = 0; g < 4; g++)
        boff[g] = sb + B_OFF + ((wn * 64 + g * 16 + (lane & 15)) * AROW + (lane >> 4) * 8) * 2;

    fill(); cpcommit();
    fill(); cpcommit();

    uint32_t roA = 0, roB = 0;
    for (int ks = 0; ks < NSTG; ks++) {
        cpwait1();
        __syncthreads();
        if (ks + 2 < NSTG) fill();
        cpcommit();

        #pragma unroll
        for (int kc = 0; kc < 2; kc++) {
            uint32_t bfrag[4][4];
            #pragma unroll
            for (int g = 0; g < 4; g++)
                ldsm4(bfrag[g], boff[g] + roB + kc * 32);
            #pragma unroll
            for (int mf = 0; mf < 4; mf++) {
                uint32_t afrag[4];
                ldsm4(afrag, aoff[mf] + roA + kc * 32);
                #pragma unroll
                for (int nf = 0; nf < 8; nf++) {
                    int g = nf >> 1, h = nf & 1;
                    mma16816h(acc[mf][nf], afrag, bfrag[g][h], bfrag[g][2 + h]);
                }
            }
        }
        roA += A_STG; if (roA == NPIPE * A_STG) roA = 0;
        roB += B_STG; if (roB == NPIPE * B_STG) roB = 0;
    }
    __syncthreads();

    // epilogue: theta = acc; exp + mask + row-sum; RED into g_excl
    const int* sy = (const int*)(smem + SY_OFF);
    float* rowacc = (float*)(smem + RA_OFF);
    #pragma unroll
    for (int mf = 0; mf < 4; mf++) {
        #pragma unroll
        for (int h = 0; h < 2; h++) {
            int row = wm * 64 + mf * 16 + h * 8 + (lane >> 2);
            int yrel = sy[row] - n0;
            float rsum = 0.f;
            #pragma unroll
            for (int nf = 0; nf < 8; nf++) {
                int nl = wn * 64 + nf * 8 + (lane & 3) * 2;
                float2 th = __half22float2(*(const __half2*)&acc[mf][nf][h]);
                float e0 = __expf(64.0f * th.x);
                float e1 = __expf(64.0f * th.y);
                rsum += (nl     == yrel) ? 0.f : e0;
                rsum += (nl + 1 == yrel) ? 0.f : e1;
            }
            rsum += __shfl_xor_sync(0xffffffffu, rsum, 1);
            rsum += __shfl_xor_sync(0xffffffffu, rsum, 2);
            if ((lane & 3) == 0) rowacc[row * 2 + wn] = rsum;
        }
    }
    __syncthreads();
    if (t < BM)
        atomicAdd(&g_excl[m0 + t], (double)(rowacc[t * 2] + rowacc[t * 2 + 1]));
}

// ---------------------------------------------------------------------------
// k3: final. One block, 512 threads: term = num - log(exp(num)+excl);
// deterministic tree mean.
// ---------------------------------------------------------------------------
__global__ __launch_bounds__(512) void k3_final(float* __restrict__ out) {
    __shared__ double sd[512];
    int t = threadIdx.x;
    double num = g_num[t];
    sd[t] = num - log(exp(num) + g_excl[t]);
    __syncthreads();
    for (int s = 256; s; s >>= 1) {
        if (t < s) sd[t] += sd[t + s];
        __syncthreads();
    }
    if (t == 0) out[0] = (float)(-sd[0] / (double)BB);
}

extern "C" void kernel_launch(void* const* d_in, const int* in_sizes, int n_in,
                              void* d_out, int out_size) {
    const float* x = (const float*)d_in[0];
    const int*   y = (const int*)d_in[1];
    const float* W = (const float*)d_in[2];

    cudaFuncSetAttribute(k2_gemm, cudaFuncAttributeMaxDynamicSharedMemorySize, SMEM_TOTAL);

    k0_init<<<1, BB>>>(y);
    k1_norm_x<<<BB, 128>>>(x, W);
    k1b_norm_w<<<CC / 8, 256>>>(W);
    k2_gemm<<<dim3(MT, NT), 256, SMEM_TOTAL>>>();
    k3_final<<<1, BB>>>((float*)d_out);
}